// round 7
// baseline (speedup 1.0000x reference)
#include <cuda_runtime.h>

#define BB 2048
#define CC 1024
#define FF 128
#define NIT 10
#define NBLK 128              // sink blocks: <=148 -> single wave, barrier-safe
#define ROWS_S (BB/NBLK)      // 16 rows per sink block
#define NB_BUILD 512          // build blocks (4 rows each)
#define BANKS 16

// Scratch (no allocs allowed -> device globals)
__device__ float    g_M[BB*CC];                   // M[b][j] = ue_b . item_emb[j]
__device__ float    g_K[BB*CC];                   // K = exp(affinity/eps)
__device__ float    g_cs[NIT+1][BANKS][CC];       // banked colsum partials per iteration
__device__ float    g_sumD;
__device__ unsigned g_bar[16];                    // one-shot grid-barrier counters

// ---------------- zero accumulators / barrier counters ----------------
__global__ void k_zero() {
    int i = blockIdx.x*blockDim.x + threadIdx.x;
    int n = (NIT+1)*BANKS*CC;
    float* cs = &g_cs[0][0][0];
    for (; i < n; i += gridDim.x*blockDim.x) cs[i] = 0.f;
    if (blockIdx.x == 0 && threadIdx.x < 16) g_bar[threadIdx.x] = 0u;
    if (blockIdx.x == 0 && threadIdx.x == 0) g_sumD = 0.f;
}

// ---------------- sum(D) ----------------
__global__ void k_sumD(const float* __restrict__ D) {
    __shared__ float sm[256];
    int t = threadIdx.x;
    float s = 0.f;
    int n4 = BB*CC/4;
    for (int i = blockIdx.x*256 + t; i < n4; i += gridDim.x*256) {
        float4 v = ((const float4*)D)[i];
        s += (v.x+v.y)+(v.z+v.w);
    }
    sm[t] = s; __syncthreads();
    for (int o = 128; o > 0; o >>= 1) { if (t < o) sm[t] += sm[t+o]; __syncthreads(); }
    if (t == 0) atomicAdd(&g_sumD, sm[0]);
}

// ---------------- GEMM: M = UE @ IE^T  (both K-major, NT) ----------------
__global__ void k_gemm(const int* __restrict__ users,
                       const float* __restrict__ item_emb,
                       const float* __restrict__ user_emb) {
    __shared__ float As[64][64];   // [k][row]
    __shared__ float Bs[64][64];   // [k][col]
    __shared__ int   ur[64];
    int t  = threadIdx.x;
    int tx = t & 15, ty = t >> 4;
    int r0 = blockIdx.y * 64, c0 = blockIdx.x * 64;
    if (t < 64) ur[t] = users[r0 + t];
    __syncthreads();

    float acc[4][4];
    #pragma unroll
    for (int i = 0; i < 4; i++)
        #pragma unroll
        for (int j = 0; j < 4; j++) acc[i][j] = 0.f;

    for (int kk = 0; kk < FF; kk += 64) {
        #pragma unroll
        for (int l = 0; l < 4; l++) {
            int idx = t + l*256;
            int row = idx & 63, kq = idx >> 6;
            float4 va = *(const float4*)&user_emb[(size_t)ur[row]*FF + kk + kq*4];
            As[kq*4+0][row] = va.x; As[kq*4+1][row] = va.y;
            As[kq*4+2][row] = va.z; As[kq*4+3][row] = va.w;
            float4 vb = *(const float4*)&item_emb[(size_t)(c0+row)*FF + kk + kq*4];
            Bs[kq*4+0][row] = vb.x; Bs[kq*4+1][row] = vb.y;
            Bs[kq*4+2][row] = vb.z; Bs[kq*4+3][row] = vb.w;
        }
        __syncthreads();
        #pragma unroll
        for (int k = 0; k < 64; k++) {
            float4 a = *(float4*)&As[k][ty*4];
            float4 b = *(float4*)&Bs[k][tx*4];
            acc[0][0] += a.x*b.x; acc[0][1] += a.x*b.y; acc[0][2] += a.x*b.z; acc[0][3] += a.x*b.w;
            acc[1][0] += a.y*b.x; acc[1][1] += a.y*b.y; acc[1][2] += a.y*b.z; acc[1][3] += a.y*b.w;
            acc[2][0] += a.z*b.x; acc[2][1] += a.z*b.y; acc[2][2] += a.z*b.z; acc[2][3] += a.z*b.w;
            acc[3][0] += a.w*b.x; acc[3][1] += a.w*b.y; acc[3][2] += a.w*b.z; acc[3][3] += a.w*b.w;
        }
        __syncthreads();
    }
    #pragma unroll
    for (int i = 0; i < 4; i++) {
        float4 o = make_float4(acc[i][0], acc[i][1], acc[i][2], acc[i][3]);
        *(float4*)&g_M[(size_t)(r0 + ty*4 + i)*CC + c0 + tx*4] = o;
    }
}

// ---------------- build: K = exp(...), u1, colsum1 partials ----------------
// 512 blocks x 4 rows, high occupancy, all loads front-batched for MLP.
__global__ void __launch_bounds__(256) k_build(const int* __restrict__ items,
                                               const float* __restrict__ D) {
    __shared__ float mrows[4][CC];   // 16 KB
    __shared__ float rs[4][256];     // 4 KB
    __shared__ float su4[4];
    int t   = threadIdx.x;
    int bid = blockIdx.x;
    int b0  = bid * 4;
    int sb  = bid & (BANKS-1);

    // front-batch: 4 M-row stages + 4 items + 4 D loads (12 independent LDG.128)
    #pragma unroll
    for (int r = 0; r < 4; r++)
        ((float4*)mrows[r])[t] = ((const float4*)g_M)[(b0 + r)*256 + t];
    int4   it4[4];
    float4 d4[4];
    #pragma unroll
    for (int r = 0; r < 4; r++) {
        it4[r] = ((const int4*)items)[(b0 + r)*256 + t];
        d4[r]  = ((const float4*)D)[(b0 + r)*256 + t];
    }
    float inv_mean = (float)(BB*CC) / g_sumD;
    __syncthreads();

    float4 kv[4];
    #pragma unroll
    for (int r = 0; r < 4; r++) {
        float4 k;
        k.x = __expf(5.f*(mrows[r][it4[r].x] - d4[r].x*inv_mean));
        k.y = __expf(5.f*(mrows[r][it4[r].y] - d4[r].y*inv_mean));
        k.z = __expf(5.f*(mrows[r][it4[r].z] - d4[r].z*inv_mean));
        k.w = __expf(5.f*(mrows[r][it4[r].w] - d4[r].w*inv_mean));
        kv[r] = k;
        ((float4*)g_K)[(b0 + r)*256 + t] = k;
        rs[r][t] = (k.x + k.y) + (k.z + k.w);
    }
    __syncthreads();
    int w = t >> 5, l = t & 31;
    if (w < 4) {
        float s = 0.f;
        #pragma unroll
        for (int j = 0; j < 8; j++) s += rs[w][l + j*32];
        #pragma unroll
        for (int o = 16; o > 0; o >>= 1) s += __shfl_down_sync(0xffffffffu, s, o);
        if (l == 0) su4[w] = 1.f / s;
    }
    __syncthreads();
    float4 acc = make_float4(0.f, 0.f, 0.f, 0.f);
    #pragma unroll
    for (int r = 0; r < 4; r++) {
        float u = su4[r];
        acc.x += kv[r].x*u; acc.y += kv[r].y*u;
        acc.z += kv[r].z*u; acc.w += kv[r].w*u;
    }
    float* cs = &g_cs[1][sb][0];
    atomicAdd(&cs[4*t+0], acc.x);
    atomicAdd(&cs[4*t+1], acc.y);
    atomicAdd(&cs[4*t+2], acc.z);
    atomicAdd(&cs[4*t+3], acc.w);
}

// ---------------- grid-wide barrier (NBLK=128 <= 148 -> always co-resident) ----
__device__ __forceinline__ void grid_barrier(int id) {
    __syncthreads();
    if (threadIdx.x == 0) {
        __threadfence();
        unsigned arrived = atomicAdd(&g_bar[id], 1u) + 1u;
        if (arrived < (unsigned)NBLK) {
            while (((volatile unsigned*)g_bar)[id] < (unsigned)NBLK) __nanosleep(64);
        }
        __threadfence();
    }
    __syncthreads();
}

// ---------------- sink: iterations 2..10 + final P, K register-resident ------
// 128 blocks x 16 rows; thread t owns cols 4t..4t+3; kv[16] = 64 regs of K.
__global__ void __launch_bounds__(256) k_sink2(const float* __restrict__ capacities,
                                               float* __restrict__ out) {
    __shared__ float rs[ROWS_S][256];   // 16 KB
    __shared__ float su[ROWS_S];
    int t   = threadIdx.x;
    int bid = blockIdx.x;
    int b0  = bid * ROWS_S;
    int sb  = bid & (BANKS-1);
    int w = t >> 5, l = t & 31;

    // load K tile into registers (16 independent LDG.128, L2-resident)
    float4 kv[ROWS_S];
    #pragma unroll
    for (int r = 0; r < ROWS_S; r++)
        kv[r] = ((const float4*)g_K)[(b0 + r)*256 + t];

    const float scaling = (float)BB / 100000.0f;
    float4 cap = ((const float4*)capacities)[t];

    for (int it = 2; it <= NIT; it++) {
        // v_{it-1} from banked partials (fresh addresses each iteration)
        float4 c = make_float4(0.f, 0.f, 0.f, 0.f);
        #pragma unroll
        for (int s8 = 0; s8 < BANKS; s8++) {
            float4 p = ((const float4*)g_cs[it-1][s8])[t];
            c.x += p.x; c.y += p.y; c.z += p.z; c.w += p.w;
        }
        float4 vv;
        vv.x = cap.x*scaling/c.x; vv.y = cap.y*scaling/c.y;
        vv.z = cap.z*scaling/c.z; vv.w = cap.w*scaling/c.w;

        #pragma unroll
        for (int r = 0; r < ROWS_S; r++)
            rs[r][t] = (kv[r].x*vv.x + kv[r].y*vv.y) + (kv[r].z*vv.z + kv[r].w*vv.w);
        __syncthreads();
        #pragma unroll
        for (int rr = 0; rr < ROWS_S; rr += 8) {
            int row = rr + w;
            float s = 0.f;
            #pragma unroll
            for (int j = 0; j < 8; j++) s += rs[row][l + j*32];
            #pragma unroll
            for (int o = 16; o > 0; o >>= 1) s += __shfl_down_sync(0xffffffffu, s, o);
            if (l == 0) su[row] = 1.f / s;
        }
        __syncthreads();
        float4 acc = make_float4(0.f, 0.f, 0.f, 0.f);
        #pragma unroll
        for (int r = 0; r < ROWS_S; r++) {
            float u = su[r];
            acc.x += kv[r].x*u; acc.y += kv[r].y*u;
            acc.z += kv[r].z*u; acc.w += kv[r].w*u;
        }
        float* csw = &g_cs[it][sb][0];
        atomicAdd(&csw[4*t+0], acc.x);
        atomicAdd(&csw[4*t+1], acc.y);
        atomicAdd(&csw[4*t+2], acc.z);
        atomicAdd(&csw[4*t+3], acc.w);
        grid_barrier(it);
    }

    // final: v10, P = K * u10 (x) v10   (su holds u10)
    {
        float4 c = make_float4(0.f, 0.f, 0.f, 0.f);
        #pragma unroll
        for (int s8 = 0; s8 < BANKS; s8++) {
            float4 p = ((const float4*)g_cs[NIT][s8])[t];
            c.x += p.x; c.y += p.y; c.z += p.z; c.w += p.w;
        }
        float4 vv;
        vv.x = cap.x*scaling/c.x; vv.y = cap.y*scaling/c.y;
        vv.z = cap.z*scaling/c.z; vv.w = cap.w*scaling/c.w;
        #pragma unroll
        for (int r = 0; r < ROWS_S; r++) {
            float u = su[r];
            float4 p;
            p.x = kv[r].x*u*vv.x; p.y = kv[r].y*u*vv.y;
            p.z = kv[r].z*u*vv.z; p.w = kv[r].w*u*vv.w;
            ((float4*)out)[(b0 + r)*256 + t] = p;
        }
    }
}

extern "C" void kernel_launch(void* const* d_in, const int* in_sizes, int n_in,
                              void* d_out, int out_size) {
    const int*   users      = (const int*)  d_in[0];
    const int*   items      = (const int*)  d_in[1];
    const float* D          = (const float*)d_in[2];
    const float* capacities = (const float*)d_in[3];
    const float* item_emb   = (const float*)d_in[4];
    const float* user_emb   = (const float*)d_in[5];
    float* out = (float*)d_out;

    k_zero<<<148, 256>>>();
    k_sumD<<<148, 256>>>(D);
    k_gemm<<<dim3(CC/64, BB/64), 256>>>(users, item_emb, user_emb);
    k_build<<<NB_BUILD, 256>>>(items, D);
    k_sink2<<<NBLK, 256>>>(capacities, out);
}

// round 8
// speedup vs baseline: 1.6780x; 1.6780x over previous
#include <cuda_runtime.h>
#include <cuda_bf16.h>
#include <cstdint>

#define BB 2048
#define CC 1024
#define FF 128
#define NIT 10
#define NBLK 128              // sink blocks: <=148 -> single wave, barrier-safe
#define ROWS_S (BB/NBLK)      // 16 rows per sink block
#define NB_BUILD 512
#define ROWS_B 4
#define BANKS 4

// Scratch (no allocs allowed -> device globals)
__device__ float          g_M[BB*CC];             // M[b][j] = ue_b . item_emb[j]
__device__ float          g_K[BB*CC];             // K = exp(affinity/eps)
__device__ float          g_cs[NIT+1][BANKS][CC]; // banked colsum partials
__device__ float          g_sumDp[160];           // per-block sumD partials
__device__ unsigned       g_bar[16];              // grid-barrier counters
__device__ __nv_bfloat16  g_A16[BB*FF];           // gathered user emb, bf16
__device__ __nv_bfloat16  g_B16[CC*FF];           // item emb, bf16

// ---------------- pre: zero + sumD partials + bf16 conversions ----------------
__global__ void __launch_bounds__(256) k_pre(const int* __restrict__ users,
                                             const float* __restrict__ user_emb,
                                             const float* __restrict__ item_emb,
                                             const float* __restrict__ D) {
    int t   = threadIdx.x;
    int tid = blockIdx.x*256 + t;
    int stride = gridDim.x*256;

    // zero colsum banks + barrier counters (overwritten-by-atomics each replay)
    for (int i = tid; i < (NIT+1)*BANKS*CC; i += stride) (&g_cs[0][0][0])[i] = 0.f;
    if (tid < 16) g_bar[tid] = 0u;

    // gather+convert A16 = bf16(user_emb[users]), 2 elems at a time
    for (int i = tid; i < BB*FF/2; i += stride) {
        int r = i >> 6;                  // 64 float2 per row
        int c = i & 63;
        float2 v = ((const float2*)(user_emb + (size_t)users[r]*FF))[c];
        ((__nv_bfloat162*)g_A16)[i] = __float22bfloat162_rn(v);
    }
    // convert B16 = bf16(item_emb)
    for (int i = tid; i < CC*FF/2; i += stride) {
        float2 v = ((const float2*)item_emb)[i];
        ((__nv_bfloat162*)g_B16)[i] = __float22bfloat162_rn(v);
    }

    // sumD partial per block (no cross-launch race: plain overwrite)
    __shared__ float sm[256];
    float s = 0.f;
    for (int i = tid; i < BB*CC/4; i += stride) {
        float4 v = ((const float4*)D)[i];
        s += (v.x+v.y)+(v.z+v.w);
    }
    sm[t] = s; __syncthreads();
    for (int o = 128; o > 0; o >>= 1) { if (t < o) sm[t] += sm[t+o]; __syncthreads(); }
    if (t == 0) g_sumDp[blockIdx.x] = sm[0];
}

// ---------------- tensor-core GEMM: M = A16 @ B16^T (fp32 accum) ----------------
// grid (16,16): block tile 128(m) x 64(n), k=128 single stage in smem.
// 8 warps = 4(m) x 2(n), warp tile 32x32, mma m16n8k16 bf16.
__device__ __forceinline__ void ldmx4(uint32_t& r0, uint32_t& r1, uint32_t& r2, uint32_t& r3,
                                      uint32_t addr) {
    asm volatile("ldmatrix.sync.aligned.m8n8.x4.shared.b16 {%0,%1,%2,%3}, [%4];"
                 : "=r"(r0), "=r"(r1), "=r"(r2), "=r"(r3) : "r"(addr));
}

__global__ void __launch_bounds__(256) k_gemm_mma() {
    __shared__ __align__(16) char smem[49152];   // A: 32KB, B: 16KB
    char* sA = smem;
    char* sB = smem + 32768;
    uint32_t sA0 = (uint32_t)__cvta_generic_to_shared(sA);
    uint32_t sB0 = (uint32_t)__cvta_generic_to_shared(sB);

    int t = threadIdx.x;
    int r0b = blockIdx.y * 128, c0b = blockIdx.x * 64;

    // load A tile: 128 rows x 256B (16 chunks of 16B), XOR swizzle chunk^(row&7)
    #pragma unroll
    for (int l = 0; l < 8; l++) {
        int id = t + l*256;              // 2048 uint4
        int r = id >> 4, c = id & 15;
        uint4 v = ((const uint4*)&g_A16[(size_t)(r0b + r)*FF])[c];
        *(uint4*)(sA + r*256 + ((c ^ (r & 7)) << 4)) = v;
    }
    // load B tile: 64 rows x 256B
    #pragma unroll
    for (int l = 0; l < 4; l++) {
        int id = t + l*256;              // 1024 uint4
        int r = id >> 4, c = id & 15;
        uint4 v = ((const uint4*)&g_B16[(size_t)(c0b + r)*FF])[c];
        *(uint4*)(sB + r*256 + ((c ^ (r & 7)) << 4)) = v;
    }
    __syncthreads();

    int wid  = t >> 5, lane = t & 31;
    int wm = wid & 3, wn = wid >> 2;     // warp tile (wm*32, wn*32)
    int jm = lane >> 3, rr = lane & 7;

    float c[2][4][4];
    #pragma unroll
    for (int mi = 0; mi < 2; mi++)
        #pragma unroll
        for (int nj = 0; nj < 4; nj++)
            #pragma unroll
            for (int e = 0; e < 4; e++) c[mi][nj][e] = 0.f;

    #pragma unroll
    for (int kk = 0; kk < 8; kk++) {
        uint32_t a[2][4];
        #pragma unroll
        for (int mi = 0; mi < 2; mi++) {
            int row = wm*32 + mi*16 + (jm & 1)*8 + rr;
            int ch  = 2*kk + (jm >> 1);
            ldmx4(a[mi][0], a[mi][1], a[mi][2], a[mi][3],
                  sA0 + row*256 + ((ch ^ (row & 7)) << 4));
        }
        uint32_t b[4][2];
        #pragma unroll
        for (int q = 0; q < 2; q++) {
            int row = wn*32 + q*16 + (jm >> 1)*8 + rr;
            int ch  = 2*kk + (jm & 1);
            uint32_t r0_, r1_, r2_, r3_;
            ldmx4(r0_, r1_, r2_, r3_, sB0 + row*256 + ((ch ^ (row & 7)) << 4));
            b[q*2][0] = r0_; b[q*2][1] = r1_;
            b[q*2+1][0] = r2_; b[q*2+1][1] = r3_;
        }
        #pragma unroll
        for (int mi = 0; mi < 2; mi++)
            #pragma unroll
            for (int nj = 0; nj < 4; nj++) {
                asm volatile(
                    "mma.sync.aligned.m16n8k16.row.col.f32.bf16.bf16.f32 "
                    "{%0,%1,%2,%3}, {%4,%5,%6,%7}, {%8,%9}, {%0,%1,%2,%3};"
                    : "+f"(c[mi][nj][0]), "+f"(c[mi][nj][1]),
                      "+f"(c[mi][nj][2]), "+f"(c[mi][nj][3])
                    : "r"(a[mi][0]), "r"(a[mi][1]), "r"(a[mi][2]), "r"(a[mi][3]),
                      "r"(b[nj][0]), "r"(b[nj][1]));
            }
    }

    // writeout: thread (g=lane>>2, tc=lane&3): rows g, g+8; cols tc*2, tc*2+1
    int g = lane >> 2, tc = lane & 3;
    #pragma unroll
    for (int mi = 0; mi < 2; mi++) {
        int row = r0b + wm*32 + mi*16 + g;
        #pragma unroll
        for (int nj = 0; nj < 4; nj++) {
            int col = c0b + wn*32 + nj*8 + tc*2;
            *(float2*)&g_M[(size_t)row*CC + col]     = make_float2(c[mi][nj][0], c[mi][nj][1]);
            *(float2*)&g_M[(size_t)(row+8)*CC + col] = make_float2(c[mi][nj][2], c[mi][nj][3]);
        }
    }
}

// ---------------- build: K = exp(...), u1, colsum1 partials ----------------
__global__ void __launch_bounds__(256) k_build(const int* __restrict__ items,
                                               const float* __restrict__ D) {
    __shared__ float mrows[ROWS_B][CC];   // 16 KB
    __shared__ float rs[ROWS_B][256];     // 4 KB
    __shared__ float red[256];
    __shared__ float su4[ROWS_B];
    int t   = threadIdx.x;
    int bid = blockIdx.x;
    int b0  = bid * ROWS_B;
    int sb  = bid & (BANKS-1);

    // reduce sumD partials (148 values)
    red[t] = (t < 148) ? g_sumDp[t] : 0.f;
    __syncthreads();
    for (int o = 128; o > 0; o >>= 1) { if (t < o) red[t] += red[t+o]; __syncthreads(); }
    float inv_mean = (float)(BB*CC) / red[0];

    // front-batch all loads
    #pragma unroll
    for (int r = 0; r < ROWS_B; r++)
        ((float4*)mrows[r])[t] = ((const float4*)g_M)[(b0 + r)*256 + t];
    int4   it4[ROWS_B];
    float4 d4[ROWS_B];
    #pragma unroll
    for (int r = 0; r < ROWS_B; r++) {
        it4[r] = ((const int4*)items)[(b0 + r)*256 + t];
        d4[r]  = ((const float4*)D)[(b0 + r)*256 + t];
    }
    __syncthreads();

    float4 kv[ROWS_B];
    #pragma unroll
    for (int r = 0; r < ROWS_B; r++) {
        float4 k;
        k.x = __expf(5.f*(mrows[r][it4[r].x] - d4[r].x*inv_mean));
        k.y = __expf(5.f*(mrows[r][it4[r].y] - d4[r].y*inv_mean));
        k.z = __expf(5.f*(mrows[r][it4[r].z] - d4[r].z*inv_mean));
        k.w = __expf(5.f*(mrows[r][it4[r].w] - d4[r].w*inv_mean));
        kv[r] = k;
        ((float4*)g_K)[(b0 + r)*256 + t] = k;
        rs[r][t] = (k.x + k.y) + (k.z + k.w);
    }
    __syncthreads();
    int w = t >> 5, l = t & 31;
    if (w < ROWS_B) {
        float s = 0.f;
        #pragma unroll
        for (int j = 0; j < 8; j++) s += rs[w][l + j*32];
        #pragma unroll
        for (int o = 16; o > 0; o >>= 1) s += __shfl_down_sync(0xffffffffu, s, o);
        if (l == 0) su4[w] = 1.f / s;
    }
    __syncthreads();
    float4 acc = make_float4(0.f, 0.f, 0.f, 0.f);
    #pragma unroll
    for (int r = 0; r < ROWS_B; r++) {
        float u = su4[r];
        acc.x += kv[r].x*u; acc.y += kv[r].y*u;
        acc.z += kv[r].z*u; acc.w += kv[r].w*u;
    }
    float* cs = &g_cs[1][sb][0];
    atomicAdd(&cs[4*t+0], acc.x);
    atomicAdd(&cs[4*t+1], acc.y);
    atomicAdd(&cs[4*t+2], acc.z);
    atomicAdd(&cs[4*t+3], acc.w);
}

// ---------------- grid barrier (128 blocks, single wave, pure spin) ----------
__device__ __forceinline__ void grid_barrier(int id) {
    __syncthreads();
    if (threadIdx.x == 0) {
        __threadfence();
        atomicAdd(&g_bar[id], 1u);
        while (((volatile unsigned*)g_bar)[id] < (unsigned)NBLK) { }
        __threadfence();
    }
    __syncthreads();
}

// ---------------- sink: iterations 2..10 + final, K register-resident --------
// 128 blocks x 512 threads, 16 rows/block, thread owns cols 2t,2t+1.
__global__ void __launch_bounds__(512) k_sink2(const float* __restrict__ capacities,
                                               float* __restrict__ out) {
    __shared__ float rs[ROWS_S][512];   // 32 KB
    __shared__ float su[ROWS_S];
    int t   = threadIdx.x;
    int bid = blockIdx.x;
    int b0  = bid * ROWS_S;
    int sb  = bid & (BANKS-1);
    int w = t >> 5, l = t & 31;         // 16 warps

    float2 kv[ROWS_S];
    #pragma unroll
    for (int r = 0; r < ROWS_S; r++)
        kv[r] = ((const float2*)g_K)[(b0 + r)*512 + t];

    const float scaling = (float)BB / 100000.0f;
    float2 cap = ((const float2*)capacities)[t];

    for (int it = 2; it <= NIT; it++) {
        float2 c = make_float2(0.f, 0.f);
        #pragma unroll
        for (int s4 = 0; s4 < BANKS; s4++) {
            float2 p = ((const float2*)g_cs[it-1][s4])[t];
            c.x += p.x; c.y += p.y;
        }
        float2 vv;
        vv.x = cap.x*scaling/c.x; vv.y = cap.y*scaling/c.y;

        #pragma unroll
        for (int r = 0; r < ROWS_S; r++)
            rs[r][t] = kv[r].x*vv.x + kv[r].y*vv.y;
        __syncthreads();
        {   // warp w reduces row w
            float s = 0.f;
            #pragma unroll
            for (int j = 0; j < 16; j++) s += rs[w][l + j*32];
            #pragma unroll
            for (int o = 16; o > 0; o >>= 1) s += __shfl_down_sync(0xffffffffu, s, o);
            if (l == 0) su[w] = 1.f / s;
        }
        __syncthreads();
        float2 acc = make_float2(0.f, 0.f);
        #pragma unroll
        for (int r = 0; r < ROWS_S; r++) {
            float u = su[r];
            acc.x += kv[r].x*u; acc.y += kv[r].y*u;
        }
        float* csw = &g_cs[it][sb][0];
        atomicAdd(&csw[2*t+0], acc.x);
        atomicAdd(&csw[2*t+1], acc.y);
        grid_barrier(it);
    }

    // final: v10, P = K * u10 (x) v10   (su holds u10)
    {
        float2 c = make_float2(0.f, 0.f);
        #pragma unroll
        for (int s4 = 0; s4 < BANKS; s4++) {
            float2 p = ((const float2*)g_cs[NIT][s4])[t];
            c.x += p.x; c.y += p.y;
        }
        float2 vv;
        vv.x = cap.x*scaling/c.x; vv.y = cap.y*scaling/c.y;
        #pragma unroll
        for (int r = 0; r < ROWS_S; r++) {
            float u = su[r];
            float2 p;
            p.x = kv[r].x*u*vv.x; p.y = kv[r].y*u*vv.y;
            ((float2*)out)[(b0 + r)*512 + t] = p;
        }
    }
}

extern "C" void kernel_launch(void* const* d_in, const int* in_sizes, int n_in,
                              void* d_out, int out_size) {
    const int*   users      = (const int*)  d_in[0];
    const int*   items      = (const int*)  d_in[1];
    const float* D          = (const float*)d_in[2];
    const float* capacities = (const float*)d_in[3];
    const float* item_emb   = (const float*)d_in[4];
    const float* user_emb   = (const float*)d_in[5];
    float* out = (float*)d_out;

    k_pre<<<148, 256>>>(users, user_emb, item_emb, D);
    k_gemm_mma<<<dim3(CC/64, BB/128), 256>>>();
    k_build<<<NB_BUILD, 256>>>(items, D);
    k_sink2<<<NBLK, 512>>>(capacities, out);
}

// round 9
// speedup vs baseline: 1.9839x; 1.1823x over previous
#include <cuda_runtime.h>
#include <cuda_bf16.h>
#include <cstdint>

#define BB 2048
#define CC 1024
#define FF 128
#define NIT 10
#define NBLK 128              // sink blocks: single wave, barrier-safe
#define ROWS_S (BB/NBLK)      // 16 rows per sink block
#define BANKS 4

// Scratch (no allocs allowed -> device globals)
__device__ float          g_M[BB*CC];             // M[b][j] = ue_b . item_emb[j]
__device__ float          g_cs[NIT+1][BANKS][CC]; // banked colsum partials
__device__ float          g_sumDp[160];           // per-block sumD partials
__device__ unsigned       g_bar[16];              // grid-barrier counters
__device__ __nv_bfloat16  g_A16[BB*FF];           // gathered user emb, bf16
__device__ __nv_bfloat16  g_B16[CC*FF];           // item emb, bf16

// ---------------- pre: zero + sumD partials + bf16 conversions ----------------
__global__ void __launch_bounds__(512) k_pre(const int* __restrict__ users,
                                             const float* __restrict__ user_emb,
                                             const float* __restrict__ item_emb,
                                             const float* __restrict__ D) {
    int t   = threadIdx.x;
    int tid = blockIdx.x*512 + t;
    int stride = gridDim.x*512;

    for (int i = tid; i < (NIT+1)*BANKS*CC; i += stride) (&g_cs[0][0][0])[i] = 0.f;
    if (tid < 16) g_bar[tid] = 0u;

    // gather+convert A16 = bf16(user_emb[users])
    for (int i = tid; i < BB*FF/2; i += stride) {
        int r = i >> 6;
        int c = i & 63;
        float2 v = ((const float2*)(user_emb + (size_t)users[r]*FF))[c];
        ((__nv_bfloat162*)g_A16)[i] = __float22bfloat162_rn(v);
    }
    for (int i = tid; i < CC*FF/2; i += stride) {
        float2 v = ((const float2*)item_emb)[i];
        ((__nv_bfloat162*)g_B16)[i] = __float22bfloat162_rn(v);
    }

    // sumD partial per block (plain overwrite: replay-safe)
    __shared__ float sm[512];
    float s = 0.f;
    for (int i = tid; i < BB*CC/4; i += stride) {
        float4 v = ((const float4*)D)[i];
        s += (v.x+v.y)+(v.z+v.w);
    }
    sm[t] = s; __syncthreads();
    for (int o = 256; o > 0; o >>= 1) { if (t < o) sm[t] += sm[t+o]; __syncthreads(); }
    if (t == 0) g_sumDp[blockIdx.x] = sm[0];
}

// ---------------- tensor-core GEMM: M = A16 @ B16^T (fp32 accum) ----------------
__device__ __forceinline__ void ldmx4(uint32_t& r0, uint32_t& r1, uint32_t& r2, uint32_t& r3,
                                      uint32_t addr) {
    asm volatile("ldmatrix.sync.aligned.m8n8.x4.shared.b16 {%0,%1,%2,%3}, [%4];"
                 : "=r"(r0), "=r"(r1), "=r"(r2), "=r"(r3) : "r"(addr));
}

__global__ void __launch_bounds__(256) k_gemm_mma() {
    __shared__ __align__(16) char smem[49152];   // A: 32KB, B: 16KB
    char* sA = smem;
    char* sB = smem + 32768;
    uint32_t sA0 = (uint32_t)__cvta_generic_to_shared(sA);
    uint32_t sB0 = (uint32_t)__cvta_generic_to_shared(sB);

    int t = threadIdx.x;
    int r0b = blockIdx.y * 128, c0b = blockIdx.x * 64;

    #pragma unroll
    for (int l = 0; l < 8; l++) {
        int id = t + l*256;
        int r = id >> 4, c = id & 15;
        uint4 v = ((const uint4*)&g_A16[(size_t)(r0b + r)*FF])[c];
        *(uint4*)(sA + r*256 + ((c ^ (r & 7)) << 4)) = v;
    }
    #pragma unroll
    for (int l = 0; l < 4; l++) {
        int id = t + l*256;
        int r = id >> 4, c = id & 15;
        uint4 v = ((const uint4*)&g_B16[(size_t)(c0b + r)*FF])[c];
        *(uint4*)(sB + r*256 + ((c ^ (r & 7)) << 4)) = v;
    }
    __syncthreads();

    int wid  = t >> 5, lane = t & 31;
    int wm = wid & 3, wn = wid >> 2;
    int jm = lane >> 3, rr = lane & 7;

    float c[2][4][4];
    #pragma unroll
    for (int mi = 0; mi < 2; mi++)
        #pragma unroll
        for (int nj = 0; nj < 4; nj++)
            #pragma unroll
            for (int e = 0; e < 4; e++) c[mi][nj][e] = 0.f;

    #pragma unroll
    for (int kk = 0; kk < 8; kk++) {
        uint32_t a[2][4];
        #pragma unroll
        for (int mi = 0; mi < 2; mi++) {
            int row = wm*32 + mi*16 + (jm & 1)*8 + rr;
            int ch  = 2*kk + (jm >> 1);
            ldmx4(a[mi][0], a[mi][1], a[mi][2], a[mi][3],
                  sA0 + row*256 + ((ch ^ (row & 7)) << 4));
        }
        uint32_t b[4][2];
        #pragma unroll
        for (int q = 0; q < 2; q++) {
            int row = wn*32 + q*16 + (jm >> 1)*8 + rr;
            int ch  = 2*kk + (jm & 1);
            uint32_t r0_, r1_, r2_, r3_;
            ldmx4(r0_, r1_, r2_, r3_, sB0 + row*256 + ((ch ^ (row & 7)) << 4));
            b[q*2][0] = r0_; b[q*2][1] = r1_;
            b[q*2+1][0] = r2_; b[q*2+1][1] = r3_;
        }
        #pragma unroll
        for (int mi = 0; mi < 2; mi++)
            #pragma unroll
            for (int nj = 0; nj < 4; nj++) {
                asm volatile(
                    "mma.sync.aligned.m16n8k16.row.col.f32.bf16.bf16.f32 "
                    "{%0,%1,%2,%3}, {%4,%5,%6,%7}, {%8,%9}, {%0,%1,%2,%3};"
                    : "+f"(c[mi][nj][0]), "+f"(c[mi][nj][1]),
                      "+f"(c[mi][nj][2]), "+f"(c[mi][nj][3])
                    : "r"(a[mi][0]), "r"(a[mi][1]), "r"(a[mi][2]), "r"(a[mi][3]),
                      "r"(b[nj][0]), "r"(b[nj][1]));
            }
    }

    int g = lane >> 2, tc = lane & 3;
    #pragma unroll
    for (int mi = 0; mi < 2; mi++) {
        int row = r0b + wm*32 + mi*16 + g;
        #pragma unroll
        for (int nj = 0; nj < 4; nj++) {
            int col = c0b + wn*32 + nj*8 + tc*2;
            *(float2*)&g_M[(size_t)row*CC + col]     = make_float2(c[mi][nj][0], c[mi][nj][1]);
            *(float2*)&g_M[(size_t)(row+8)*CC + col] = make_float2(c[mi][nj][2], c[mi][nj][3]);
        }
    }
}

// ------- grid barrier: red.release arrival + ld.acquire spin (no MEMBAR) -------
__device__ __forceinline__ void grid_barrier(int id) {
    __syncthreads();
    if (threadIdx.x == 0) {
        unsigned* p = &g_bar[id];
        asm volatile("red.release.gpu.global.add.u32 [%0], %1;"
                     :: "l"(p), "r"(1u) : "memory");
        unsigned v;
        do {
            asm volatile("ld.acquire.gpu.global.u32 %0, [%1];"
                         : "=r"(v) : "l"(p) : "memory");
        } while (v < (unsigned)NBLK);
    }
    __syncthreads();
}

// ------- fused sink: K build + iter1 + iters 2..10 + final P ------------------
// 128 blocks x 512 threads, 16 rows/block; thread t owns cols 2t,2t+1.
// kv[16] float2 = K tile in registers. sbuf reused: M-row stage, then rowsum scratch.
__global__ void __launch_bounds__(512, 1)
k_sink(const int* __restrict__ items, const float* __restrict__ D,
       const float* __restrict__ capacities, float* __restrict__ out) {
    __shared__ __align__(16) float sbuf[8*CC];   // 32 KB: mrows (8 rows) / rs[16][512]
    __shared__ float su[ROWS_S];
    int t   = threadIdx.x;
    int bid = blockIdx.x;
    int b0  = bid * ROWS_S;
    int sb  = bid & (BANKS-1);
    int w = t >> 5, l = t & 31;

    // ---- sumD reduce (148 partials) ----
    sbuf[t] = (t < 148) ? g_sumDp[t] : 0.f;
    __syncthreads();
    for (int o = 256; o > 0; o >>= 1) { if (t < o) sbuf[t] += sbuf[t+o]; __syncthreads(); }
    float inv_mean = (float)(BB*CC) / sbuf[0];
    __syncthreads();

    // ---- build K in registers: two 8-row passes over smem-staged M ----
    float2 kv[ROWS_S];
    #pragma unroll
    for (int half = 0; half < 2; half++) {
        #pragma unroll
        for (int r = 0; r < 8; r++)
            ((float2*)&sbuf[r*CC])[t] = ((const float2*)g_M)[(size_t)(b0 + half*8 + r)*512 + t];
        __syncthreads();
        #pragma unroll
        for (int r = 0; r < 8; r++) {
            int row = half*8 + r;
            int2   it2 = ((const int2*)items)[(size_t)(b0+row)*512 + t];
            float2 d2  = ((const float2*)D)[(size_t)(b0+row)*512 + t];
            kv[row].x = __expf(5.f*(sbuf[r*CC + it2.x] - d2.x*inv_mean));
            kv[row].y = __expf(5.f*(sbuf[r*CC + it2.y] - d2.y*inv_mean));
        }
        __syncthreads();
    }

    const float scaling = (float)BB / 100000.0f;
    float2 cap = ((const float2*)capacities)[t];

    // ---- iteration 1: u1 = 1/rowsum(K), colsum1 partials ----
    #pragma unroll
    for (int r = 0; r < ROWS_S; r++)
        sbuf[r*512 + t] = kv[r].x + kv[r].y;
    __syncthreads();
    {
        float s = 0.f;
        #pragma unroll
        for (int j = 0; j < 16; j++) s += sbuf[w*512 + l + j*32];
        #pragma unroll
        for (int o = 16; o > 0; o >>= 1) s += __shfl_down_sync(0xffffffffu, s, o);
        if (l == 0) su[w] = 1.f / s;
    }
    __syncthreads();
    {
        float2 acc = make_float2(0.f, 0.f);
        #pragma unroll
        for (int r = 0; r < ROWS_S; r++) {
            float u = su[r];
            acc.x += kv[r].x*u; acc.y += kv[r].y*u;
        }
        float* cs = &g_cs[1][sb][0];
        atomicAdd(&cs[2*t+0], acc.x);
        atomicAdd(&cs[2*t+1], acc.y);
    }
    grid_barrier(1);

    // ---- iterations 2..10 ----
    for (int it = 2; it <= NIT; it++) {
        float2 c = make_float2(0.f, 0.f);
        #pragma unroll
        for (int s4 = 0; s4 < BANKS; s4++) {
            float2 p = ((const float2*)g_cs[it-1][s4])[t];
            c.x += p.x; c.y += p.y;
        }
        float2 vv;
        vv.x = cap.x*scaling/c.x; vv.y = cap.y*scaling/c.y;

        #pragma unroll
        for (int r = 0; r < ROWS_S; r++)
            sbuf[r*512 + t] = kv[r].x*vv.x + kv[r].y*vv.y;
        __syncthreads();
        {
            float s = 0.f;
            #pragma unroll
            for (int j = 0; j < 16; j++) s += sbuf[w*512 + l + j*32];
            #pragma unroll
            for (int o = 16; o > 0; o >>= 1) s += __shfl_down_sync(0xffffffffu, s, o);
            if (l == 0) su[w] = 1.f / s;
        }
        __syncthreads();
        float2 acc = make_float2(0.f, 0.f);
        #pragma unroll
        for (int r = 0; r < ROWS_S; r++) {
            float u = su[r];
            acc.x += kv[r].x*u; acc.y += kv[r].y*u;
        }
        float* csw = &g_cs[it][sb][0];
        atomicAdd(&csw[2*t+0], acc.x);
        atomicAdd(&csw[2*t+1], acc.y);
        grid_barrier(it);
    }

    // ---- final: v10, P = K * u10 (x) v10 (su holds u10) ----
    {
        float2 c = make_float2(0.f, 0.f);
        #pragma unroll
        for (int s4 = 0; s4 < BANKS; s4++) {
            float2 p = ((const float2*)g_cs[NIT][s4])[t];
            c.x += p.x; c.y += p.y;
        }
        float2 vv;
        vv.x = cap.x*scaling/c.x; vv.y = cap.y*scaling/c.y;
        #pragma unroll
        for (int r = 0; r < ROWS_S; r++) {
            float u = su[r];
            float2 p;
            p.x = kv[r].x*u*vv.x; p.y = kv[r].y*u*vv.y;
            ((float2*)out)[(size_t)(b0 + r)*512 + t] = p;
        }
    }
}

extern "C" void kernel_launch(void* const* d_in, const int* in_sizes, int n_in,
                              void* d_out, int out_size) {
    const int*   users      = (const int*)  d_in[0];
    const int*   items      = (const int*)  d_in[1];
    const float* D          = (const float*)d_in[2];
    const float* capacities = (const float*)d_in[3];
    const float* item_emb   = (const float*)d_in[4];
    const float* user_emb   = (const float*)d_in[5];
    float* out = (float*)d_out;

    k_pre<<<148, 512>>>(users, user_emb, item_emb, D);
    k_gemm_mma<<<dim3(CC/64, BB/128), 256>>>();
    k_sink<<<NBLK, 512>>>(items, D, capacities, out);
}

// round 10
// speedup vs baseline: 2.0453x; 1.0309x over previous
#include <cuda_runtime.h>
#include <cuda_bf16.h>
#include <cstdint>

#define BB 2048
#define CC 1024
#define FF 128
#define NIT 10
#define NBLK 128              // sink blocks: single wave, barrier-safe
#define ROWS_S (BB/NBLK)      // 16 rows per sink block
#define BANKS 4

// Scratch (no allocs allowed -> device globals)
__device__ float    g_M[BB*CC];             // M[b][j] = ue_b . item_emb[j]
__device__ float    g_cs[NIT+1][BANKS][CC]; // banked colsum partials
__device__ float    g_sumD;                 // global sum of D
__device__ unsigned g_bar[16];              // grid-barrier counters

// ---------------- tensor-core GEMM: M = bf16(UE[users]) @ bf16(IE)^T ----------
// grid (16,16): block tile 128(m) x 64(n), k=128 single stage.
// Loads fp32 directly (gather for A), converts to bf16 in-register.
// Also zeroes colsum banks / barrier counters / g_sumD (runs before k_sink).
__device__ __forceinline__ void ldmx4(uint32_t& r0, uint32_t& r1, uint32_t& r2, uint32_t& r3,
                                      uint32_t addr) {
    asm volatile("ldmatrix.sync.aligned.m8n8.x4.shared.b16 {%0,%1,%2,%3}, [%4];"
                 : "=r"(r0), "=r"(r1), "=r"(r2), "=r"(r3) : "r"(addr));
}

__device__ __forceinline__ uint32_t bf2u(float x, float y) {
    __nv_bfloat162 h = __floats2bfloat162_rn(x, y);
    return *reinterpret_cast<uint32_t*>(&h);
}

__global__ void __launch_bounds__(256) k_gemm_mma(const int* __restrict__ users,
                                                  const float* __restrict__ user_emb,
                                                  const float* __restrict__ item_emb) {
    __shared__ __align__(16) char smem[49152];   // A: 32KB (128x256B), B: 16KB (64x256B)
    char* sA = smem;
    char* sB = smem + 32768;
    uint32_t sA0 = (uint32_t)__cvta_generic_to_shared(sA);
    uint32_t sB0 = (uint32_t)__cvta_generic_to_shared(sB);

    int t = threadIdx.x;
    int r0b = blockIdx.y * 128, c0b = blockIdx.x * 64;

    // ---- zero accumulators (176KB spread over 256 blocks; done before sink) ----
    {
        int lin = (blockIdx.y * gridDim.x + blockIdx.x) * 256 + t;
        int n = (NIT+1)*BANKS*CC;
        if (lin < n) (&g_cs[0][0][0])[lin] = 0.f;
        if (lin < 16) g_bar[lin] = 0u;
        if (lin == 0) g_sumD = 0.f;
    }

    // ---- A tile: gather rows via users, fp32 -> bf16, swizzled smem ----
    #pragma unroll
    for (int l = 0; l < 16; l++) {
        int id = t + l*256;              // 4096 uint4 (128 rows x 32)
        int r = id >> 5, c = id & 31;
        int urow = users[r0b + r];
        uint4 vi = ((const uint4*)(user_emb + (size_t)urow*FF))[c];
        float4 v = *reinterpret_cast<float4*>(&vi);
        uint2 st = make_uint2(bf2u(v.x, v.y), bf2u(v.z, v.w));
        *(uint2*)(sA + r*256 + (((c>>1) ^ (r & 7)) << 4) + ((c & 1) << 3)) = st;
    }
    // ---- B tile: fp32 -> bf16 ----
    #pragma unroll
    for (int l = 0; l < 8; l++) {
        int id = t + l*256;              // 2048 uint4 (64 rows x 32)
        int r = id >> 5, c = id & 31;
        uint4 vi = ((const uint4*)(item_emb + (size_t)(c0b + r)*FF))[c];
        float4 v = *reinterpret_cast<float4*>(&vi);
        uint2 st = make_uint2(bf2u(v.x, v.y), bf2u(v.z, v.w));
        *(uint2*)(sB + r*256 + (((c>>1) ^ (r & 7)) << 4) + ((c & 1) << 3)) = st;
    }
    __syncthreads();

    int wid  = t >> 5, lane = t & 31;
    int wm = wid & 3, wn = wid >> 2;
    int jm = lane >> 3, rr = lane & 7;

    float c[2][4][4];
    #pragma unroll
    for (int mi = 0; mi < 2; mi++)
        #pragma unroll
        for (int nj = 0; nj < 4; nj++)
            #pragma unroll
            for (int e = 0; e < 4; e++) c[mi][nj][e] = 0.f;

    #pragma unroll
    for (int kk = 0; kk < 8; kk++) {
        uint32_t a[2][4];
        #pragma unroll
        for (int mi = 0; mi < 2; mi++) {
            int row = wm*32 + mi*16 + (jm & 1)*8 + rr;
            int ch  = 2*kk + (jm >> 1);
            ldmx4(a[mi][0], a[mi][1], a[mi][2], a[mi][3],
                  sA0 + row*256 + ((ch ^ (row & 7)) << 4));
        }
        uint32_t b[4][2];
        #pragma unroll
        for (int q = 0; q < 2; q++) {
            int row = wn*32 + q*16 + (jm >> 1)*8 + rr;
            int ch  = 2*kk + (jm & 1);
            uint32_t r0_, r1_, r2_, r3_;
            ldmx4(r0_, r1_, r2_, r3_, sB0 + row*256 + ((ch ^ (row & 7)) << 4));
            b[q*2][0] = r0_; b[q*2][1] = r1_;
            b[q*2+1][0] = r2_; b[q*2+1][1] = r3_;
        }
        #pragma unroll
        for (int mi = 0; mi < 2; mi++)
            #pragma unroll
            for (int nj = 0; nj < 4; nj++) {
                asm volatile(
                    "mma.sync.aligned.m16n8k16.row.col.f32.bf16.bf16.f32 "
                    "{%0,%1,%2,%3}, {%4,%5,%6,%7}, {%8,%9}, {%0,%1,%2,%3};"
                    : "+f"(c[mi][nj][0]), "+f"(c[mi][nj][1]),
                      "+f"(c[mi][nj][2]), "+f"(c[mi][nj][3])
                    : "r"(a[mi][0]), "r"(a[mi][1]), "r"(a[mi][2]), "r"(a[mi][3]),
                      "r"(b[nj][0]), "r"(b[nj][1]));
            }
    }

    int g = lane >> 2, tc = lane & 3;
    #pragma unroll
    for (int mi = 0; mi < 2; mi++) {
        int row = r0b + wm*32 + mi*16 + g;
        #pragma unroll
        for (int nj = 0; nj < 4; nj++) {
            int col = c0b + wn*32 + nj*8 + tc*2;
            *(float2*)&g_M[(size_t)row*CC + col]     = make_float2(c[mi][nj][0], c[mi][nj][1]);
            *(float2*)&g_M[(size_t)(row+8)*CC + col] = make_float2(c[mi][nj][2], c[mi][nj][3]);
        }
    }
}

// ------- grid barrier: red.release arrival + ld.acquire spin (no MEMBAR) -------
__device__ __forceinline__ void grid_barrier(int id) {
    __syncthreads();
    if (threadIdx.x == 0) {
        unsigned* p = &g_bar[id];
        asm volatile("red.release.gpu.global.add.u32 [%0], %1;"
                     :: "l"(p), "r"(1u) : "memory");
        unsigned v;
        do {
            asm volatile("ld.acquire.gpu.global.u32 %0, [%1];"
                         : "=r"(v) : "l"(p) : "memory");
        } while (v < (unsigned)NBLK);
    }
    __syncthreads();
}

// ------- fused sink: sumD + K build + iter1 + iters 2..10 + final P -----------
// 128 blocks x 512 threads, 16 rows/block; thread t owns cols 2t,2t+1.
// D and K tiles live in registers across the whole kernel.
__global__ void __launch_bounds__(512, 1)
k_sink(const int* __restrict__ items, const float* __restrict__ D,
       const float* __restrict__ capacities, float* __restrict__ out) {
    __shared__ __align__(16) float sbuf[8*CC];   // 32 KB: mrows stage / rowsum scratch
    __shared__ float su[ROWS_S];
    int t   = threadIdx.x;
    int bid = blockIdx.x;
    int b0  = bid * ROWS_S;
    int sb  = bid & (BANKS-1);
    int w = t >> 5, l = t & 31;

    // ---- phase 0: load D into registers, global sumD, barrier ----
    float2 d2[ROWS_S];
    #pragma unroll
    for (int r = 0; r < ROWS_S; r++)
        d2[r] = ((const float2*)D)[(size_t)(b0 + r)*512 + t];
    {
        float s = 0.f;
        #pragma unroll
        for (int r = 0; r < ROWS_S; r++) s += d2[r].x + d2[r].y;
        sbuf[t] = s; __syncthreads();
        for (int o = 256; o > 0; o >>= 1) { if (t < o) sbuf[t] += sbuf[t+o]; __syncthreads(); }
        if (t == 0) atomicAdd(&g_sumD, sbuf[0]);
    }
    grid_barrier(0);
    float inv_mean = (float)(BB*CC) / *((volatile float*)&g_sumD);
    __syncthreads();

    // ---- build K in registers: two 8-row passes over smem-staged M ----
    float2 kv[ROWS_S];
    #pragma unroll
    for (int half = 0; half < 2; half++) {
        #pragma unroll
        for (int r = 0; r < 8; r++)
            ((float2*)&sbuf[r*CC])[t] = ((const float2*)g_M)[(size_t)(b0 + half*8 + r)*512 + t];
        __syncthreads();
        #pragma unroll
        for (int r = 0; r < 8; r++) {
            int row = half*8 + r;
            int2 it2 = ((const int2*)items)[(size_t)(b0+row)*512 + t];
            kv[row].x = __expf(5.f*(sbuf[r*CC + it2.x] - d2[row].x*inv_mean));
            kv[row].y = __expf(5.f*(sbuf[r*CC + it2.y] - d2[row].y*inv_mean));
        }
        __syncthreads();
    }

    const float scaling = (float)BB / 100000.0f;
    float2 cap = ((const float2*)capacities)[t];

    // ---- iteration 1: u1 = 1/rowsum(K), colsum1 partials ----
    #pragma unroll
    for (int r = 0; r < ROWS_S; r++)
        sbuf[r*512 + t] = kv[r].x + kv[r].y;
    __syncthreads();
    {
        float s = 0.f;
        #pragma unroll
        for (int j = 0; j < 16; j++) s += sbuf[w*512 + l + j*32];
        #pragma unroll
        for (int o = 16; o > 0; o >>= 1) s += __shfl_down_sync(0xffffffffu, s, o);
        if (l == 0) su[w] = 1.f / s;
    }
    __syncthreads();
    {
        float2 acc = make_float2(0.f, 0.f);
        #pragma unroll
        for (int r = 0; r < ROWS_S; r++) {
            float u = su[r];
            acc.x += kv[r].x*u; acc.y += kv[r].y*u;
        }
        float* cs = &g_cs[1][sb][0];
        atomicAdd(&cs[2*t+0], acc.x);
        atomicAdd(&cs[2*t+1], acc.y);
    }
    grid_barrier(1);

    // ---- iterations 2..10 ----
    for (int it = 2; it <= NIT; it++) {
        float2 c = make_float2(0.f, 0.f);
        #pragma unroll
        for (int s4 = 0; s4 < BANKS; s4++) {
            float2 p = ((const float2*)g_cs[it-1][s4])[t];
            c.x += p.x; c.y += p.y;
        }
        float2 vv;
        vv.x = cap.x*scaling/c.x; vv.y = cap.y*scaling/c.y;

        #pragma unroll
        for (int r = 0; r < ROWS_S; r++)
            sbuf[r*512 + t] = kv[r].x*vv.x + kv[r].y*vv.y;
        __syncthreads();
        {
            float s = 0.f;
            #pragma unroll
            for (int j = 0; j < 16; j++) s += sbuf[w*512 + l + j*32];
            #pragma unroll
            for (int o = 16; o > 0; o >>= 1) s += __shfl_down_sync(0xffffffffu, s, o);
            if (l == 0) su[w] = 1.f / s;
        }
        __syncthreads();
        float2 acc = make_float2(0.f, 0.f);
        #pragma unroll
        for (int r = 0; r < ROWS_S; r++) {
            float u = su[r];
            acc.x += kv[r].x*u; acc.y += kv[r].y*u;
        }
        float* csw = &g_cs[it][sb][0];
        atomicAdd(&csw[2*t+0], acc.x);
        atomicAdd(&csw[2*t+1], acc.y);
        grid_barrier(it);
    }

    // ---- final: v10, P = K * u10 (x) v10 (su holds u10) ----
    {
        float2 c = make_float2(0.f, 0.f);
        #pragma unroll
        for (int s4 = 0; s4 < BANKS; s4++) {
            float2 p = ((const float2*)g_cs[NIT][s4])[t];
            c.x += p.x; c.y += p.y;
        }
        float2 vv;
        vv.x = cap.x*scaling/c.x; vv.y = cap.y*scaling/c.y;
        #pragma unroll
        for (int r = 0; r < ROWS_S; r++) {
            float u = su[r];
            float2 p;
            p.x = kv[r].x*u*vv.x; p.y = kv[r].y*u*vv.y;
            ((float2*)out)[(size_t)(b0 + r)*512 + t] = p;
        }
    }
}

extern "C" void kernel_launch(void* const* d_in, const int* in_sizes, int n_in,
                              void* d_out, int out_size) {
    const int*   users      = (const int*)  d_in[0];
    const int*   items      = (const int*)  d_in[1];
    const float* D          = (const float*)d_in[2];
    const float* capacities = (const float*)d_in[3];
    const float* item_emb   = (const float*)d_in[4];
    const float* user_emb   = (const float*)d_in[5];
    float* out = (float*)d_out;

    k_gemm_mma<<<dim3(CC/64, BB/128), 256>>>(users, user_emb, item_emb);
    k_sink<<<NBLK, 512>>>(items, D, capacities, out);
}